// round 3
// baseline (speedup 1.0000x reference)
#include <cuda_runtime.h>
#include <cuda_fp16.h>

// Problem constants
#define NB   32      // batch
#define NIN  2048    // input capsules
#define ROW  1024    // NOUT*DD floats per (b,i) row
#define SLICES 8     // blocks per batch item
#define WPBLK  8     // warps per block
#define IPW  32      // input rows per warp (NIN / (SLICES*WPBLK))

// Scratch (static device memory; no runtime allocation)
__device__ float   g_partials[NB * SLICES * ROW];          // 1 MB, L2-resident
__device__ float   g_ow[NB * ROW];                         // out0 / out0+out1
__device__ __half2 g_xh[(size_t)NB * NIN * (ROW / 2)];     // 128 MB fp16 copy of x
__device__ int     g_cnt[NB];                              // zero-init; self-resetting

union HF { __half2 h; float f; };

// ---------------------------------------------------------------------------
// Fused tail: in-block reduce (8 warps -> 1 partial), then the LAST block of
// each batch reduces the 8 per-block partials in fixed order, adds bias,
// squashes, updates g_ow / writes output, and resets the counter.
// ---------------------------------------------------------------------------
__device__ __forceinline__ void finish_tail(
    int b, int slice, float4 acc[8], int wloc, int lane,
    const float* __restrict__ bias, float* __restrict__ dout,
    int ow_mode, int final_out)
{
    __shared__ float4 sbuf[WPBLK * 256];   // 32 KB
#pragma unroll
    for (int k = 0; k < 8; k++) sbuf[wloc * 256 + lane + 32 * k] = acc[k];
    __syncthreads();

    const int t = threadIdx.x;
    float4 s = make_float4(0.f, 0.f, 0.f, 0.f);
#pragma unroll
    for (int w2 = 0; w2 < WPBLK; w2++) {
        float4 v = sbuf[w2 * 256 + t];
        s.x += v.x; s.y += v.y; s.z += v.z; s.w += v.w;
    }
    reinterpret_cast<float4*>(g_partials)[((size_t)b * SLICES + slice) * 256 + t] = s;
    __threadfence();

    __shared__ int isLast;
    if (t == 0) {
        int old = atomicAdd(&g_cnt[b], 1);
        isLast = (old == SLICES - 1);
    }
    __syncthreads();
    if (!isLast) return;

    // Last block for this batch: all 8 partials are visible (fence + atomic).
    const float4* pp = reinterpret_cast<const float4*>(g_partials) + (size_t)b * SLICES * 256;
    float4 r = make_float4(0.f, 0.f, 0.f, 0.f);
#pragma unroll
    for (int s2 = 0; s2 < SLICES; s2++) {
        float4 v = __ldcg(pp + s2 * 256 + t);   // L2 (bypass L1; other SMs wrote)
        r.x += v.x; r.y += v.y; r.z += v.z; r.w += v.w;
    }
    float4 bb = reinterpret_cast<const float4*>(bias)[t];
    r.x += bb.x; r.y += bb.y; r.z += bb.z; r.w += bb.w;

    // squash over d=16 (4 threads per capsule j)
    float n2 = r.x * r.x + r.y * r.y + r.z * r.z + r.w * r.w;
    n2 += __shfl_xor_sync(0xffffffffu, n2, 1);
    n2 += __shfl_xor_sync(0xffffffffu, n2, 2);
    float scale = n2 / ((1.0f + n2) * sqrtf(n2 + 1e-7f));
    float4 o = make_float4(r.x * scale, r.y * scale, r.z * scale, r.w * scale);

    if (final_out)
        reinterpret_cast<float4*>(dout)[b * 256 + t] = o;
    if (ow_mode == 1) {
        reinterpret_cast<float4*>(g_ow)[b * 256 + t] = o;
    } else if (ow_mode == 2) {
        float4 c = reinterpret_cast<const float4*>(g_ow)[b * 256 + t];
        c.x += o.x; c.y += o.y; c.z += o.z; c.w += o.w;
        reinterpret_cast<float4*>(g_ow)[b * 256 + t] = c;
    }

    if (t == 0) g_cnt[b] = 0;   // reset for next round / next graph replay
}

// ---------------------------------------------------------------------------
// Round 0: uniform weights (softmax of zero priors = 1/64). Reads fp32 input,
// writes fp16 shadow copy, accumulates the mean, fused reduce+squash tail.
// ---------------------------------------------------------------------------
__global__ void __launch_bounds__(256, 2)
pass0(const float* __restrict__ x, const float* __restrict__ bias, float* __restrict__ dout)
{
    const int b     = blockIdx.x >> 3;
    const int slice = blockIdx.x & 7;
    const int wloc  = threadIdx.x >> 5;
    const int wb    = (slice << 3) | wloc;
    const int lane  = threadIdx.x & 31;

    float4 acc[8];
#pragma unroll
    for (int k = 0; k < 8; k++) acc[k] = make_float4(0.f, 0.f, 0.f, 0.f);

    const float4* base = reinterpret_cast<const float4*>(x)
        + ((size_t)b * NIN + (size_t)wb * IPW) * (ROW / 4);
    float2* hbase = reinterpret_cast<float2*>(g_xh)
        + ((size_t)b * NIN + (size_t)wb * IPW) * (ROW / 4);   // 1 float2 = 4 halves

    for (int ii = 0; ii < IPW; ii++) {
        const float4* rowp = base + (size_t)ii * (ROW / 4);
        float2* hrow = hbase + (size_t)ii * (ROW / 4);
#pragma unroll
        for (int k = 0; k < 8; k++) {
            float4 v = __ldcs(rowp + lane + 32 * k);
            // fp16 shadow store (streaming)
            HF a0, a1;
            a0.h = __floats2half2_rn(v.x, v.y);
            a1.h = __floats2half2_rn(v.z, v.w);
            float2 st; st.x = a0.f; st.y = a1.f;
            __stcs(hrow + lane + 32 * k, st);
            // uniform accumulate (scale by 1/64 at the end)
            acc[k].x += v.x; acc[k].y += v.y; acc[k].z += v.z; acc[k].w += v.w;
        }
    }
#pragma unroll
    for (int k = 0; k < 8; k++) {
        acc[k].x *= 0.015625f; acc[k].y *= 0.015625f;
        acc[k].z *= 0.015625f; acc[k].w *= 0.015625f;
    }

    finish_tail(b, slice, acc, wloc, lane, bias, dout, /*ow_mode=*/1, /*final=*/0);
}

// ---------------------------------------------------------------------------
// Rounds 1 & 2: read fp16 shadow copy; weights = softmax_j(dot(x_ij, g_ow_j)).
// ---------------------------------------------------------------------------
__global__ void __launch_bounds__(256, 2)
passH(const float* __restrict__ bias, float* __restrict__ dout,
      int ow_mode, int final_out)
{
    const int b     = blockIdx.x >> 3;
    const int slice = blockIdx.x & 7;
    const int wloc  = threadIdx.x >> 5;
    const int wb    = (slice << 3) | wloc;
    const int lane  = threadIdx.x & 31;

    float4 w[8];
    const float4* owp = reinterpret_cast<const float4*>(g_ow) + (size_t)b * (ROW / 4);
#pragma unroll
    for (int k = 0; k < 8; k++) w[k] = owp[lane + 32 * k];

    float4 acc[8];
#pragma unroll
    for (int k = 0; k < 8; k++) acc[k] = make_float4(0.f, 0.f, 0.f, 0.f);

    const float2* hbase = reinterpret_cast<const float2*>(g_xh)
        + ((size_t)b * NIN + (size_t)wb * IPW) * (ROW / 4);

    for (int ii = 0; ii < IPW; ii++) {
        const float2* hrow = hbase + (size_t)ii * (ROW / 4);
        float4 xv[8];
#pragma unroll
        for (int k = 0; k < 8; k++) {
            float2 raw = __ldcs(hrow + lane + 32 * k);
            HF u0, u1; u0.f = raw.x; u1.f = raw.y;
            float2 lo = __half22float2(u0.h);
            float2 hi = __half22float2(u1.h);
            xv[k] = make_float4(lo.x, lo.y, hi.x, hi.y);
        }

        float p[8];
#pragma unroll
        for (int k = 0; k < 8; k++) {
            float t = xv[k].x * w[k].x + xv[k].y * w[k].y
                    + xv[k].z * w[k].z + xv[k].w * w[k].w;
            t += __shfl_xor_sync(0xffffffffu, t, 1);
            t += __shfl_xor_sync(0xffffffffu, t, 2);
            p[k] = t;   // dot over d=16, replicated within 4-lane group
        }
        // softmax over 64 j
        float m = p[0];
#pragma unroll
        for (int k = 1; k < 8; k++) m = fmaxf(m, p[k]);
        m = fmaxf(m, __shfl_xor_sync(0xffffffffu, m, 4));
        m = fmaxf(m, __shfl_xor_sync(0xffffffffu, m, 8));
        m = fmaxf(m, __shfl_xor_sync(0xffffffffu, m, 16));
        float a[8], s = 0.f;
#pragma unroll
        for (int k = 0; k < 8; k++) { a[k] = __expf(p[k] - m); s += a[k]; }
        s += __shfl_xor_sync(0xffffffffu, s, 4);
        s += __shfl_xor_sync(0xffffffffu, s, 8);
        s += __shfl_xor_sync(0xffffffffu, s, 16);
        float inv = 1.0f / s;
#pragma unroll
        for (int k = 0; k < 8; k++) {
            float ak = a[k] * inv;
            acc[k].x = fmaf(ak, xv[k].x, acc[k].x);
            acc[k].y = fmaf(ak, xv[k].y, acc[k].y);
            acc[k].z = fmaf(ak, xv[k].z, acc[k].z);
            acc[k].w = fmaf(ak, xv[k].w, acc[k].w);
        }
    }

    finish_tail(b, slice, acc, wloc, lane, bias, dout, ow_mode, final_out);
}

extern "C" void kernel_launch(void* const* d_in, const int* in_sizes, int n_in,
                              void* d_out, int out_size)
{
    const float* x    = (const float*)d_in[0];   // [32, 2048, 64, 16]
    const float* bias = (const float*)d_in[1];   // [64, 16]
    float* out = (float*)d_out;                  // [32, 64, 16]

    (void)in_sizes; (void)n_in; (void)out_size;

    dim3 g(NB * SLICES), blk(256);

    // Round 0: uniform weights; also emit fp16 shadow copy; g_ow = out0
    pass0<<<g, blk>>>(x, bias, out);
    // Round 1: softmax(dot(x, out0)); g_ow = out0 + out1
    passH<<<g, blk>>>(bias, out, /*ow_mode=*/2, /*final=*/0);
    // Round 2: softmax(dot(x, out0+out1)); write output (priors are linear in outs)
    passH<<<g, blk>>>(bias, out, /*ow_mode=*/0, /*final=*/1);
}

// round 4
// speedup vs baseline: 1.3757x; 1.3757x over previous
#include <cuda_runtime.h>

// Problem constants
#define NB   32      // batch
#define NIN  2048    // input capsules
#define ROW  1024    // NOUT*DD floats per (b,i) row
#define SLICES 16    // blocks per batch item
#define WPBLK  8     // warps per block
#define IPW  16      // input rows per warp (NIN / (SLICES*WPBLK))

// Scratch (static device memory; no runtime allocation)
__device__ float g_partials[NB * SLICES * ROW];  // 2 MB, L2-resident
__device__ float g_ow[NB * ROW];                 // out0 (round1) / out0+out1 (round2)
__device__ int   g_cnt[NB];                      // zero-init; self-resetting

// ---------------------------------------------------------------------------
// Fused tail: in-block reduce (8 warps -> 1 partial per block), then the LAST
// block of each batch reduces the SLICES partials in fixed order, adds bias,
// squashes, updates g_ow / writes output, resets the counter (replay-safe).
// ---------------------------------------------------------------------------
__device__ __forceinline__ void finish_tail(
    int b, int slice, float4 acc[8], int wloc, int lane,
    const float* __restrict__ bias, float* __restrict__ dout,
    int ow_mode, int final_out)
{
    __shared__ float4 sbuf[WPBLK * 256];   // 32 KB
#pragma unroll
    for (int k = 0; k < 8; k++) sbuf[wloc * 256 + lane + 32 * k] = acc[k];
    __syncthreads();

    const int t = threadIdx.x;
    float4 s = make_float4(0.f, 0.f, 0.f, 0.f);
#pragma unroll
    for (int w2 = 0; w2 < WPBLK; w2++) {
        float4 v = sbuf[w2 * 256 + t];
        s.x += v.x; s.y += v.y; s.z += v.z; s.w += v.w;
    }
    reinterpret_cast<float4*>(g_partials)[((size_t)b * SLICES + slice) * 256 + t] = s;
    __threadfence();

    __shared__ int isLast;
    if (t == 0) {
        int old = atomicAdd(&g_cnt[b], 1);
        isLast = (old == SLICES - 1);
    }
    __syncthreads();
    if (!isLast) return;

    // Last block for this batch: all partials visible (fence + atomic order).
    const float4* pp = reinterpret_cast<const float4*>(g_partials) + (size_t)b * SLICES * 256;
    float4 r = make_float4(0.f, 0.f, 0.f, 0.f);
#pragma unroll
    for (int s2 = 0; s2 < SLICES; s2++) {
        float4 v = __ldcg(pp + s2 * 256 + t);   // L2 (other SMs wrote these)
        r.x += v.x; r.y += v.y; r.z += v.z; r.w += v.w;
    }
    float4 bb = reinterpret_cast<const float4*>(bias)[t];
    r.x += bb.x; r.y += bb.y; r.z += bb.z; r.w += bb.w;

    // squash over d=16 (4 threads per capsule j)
    float n2 = r.x * r.x + r.y * r.y + r.z * r.z + r.w * r.w;
    n2 += __shfl_xor_sync(0xffffffffu, n2, 1);
    n2 += __shfl_xor_sync(0xffffffffu, n2, 2);
    float scale = n2 / ((1.0f + n2) * sqrtf(n2 + 1e-7f));
    float4 o = make_float4(r.x * scale, r.y * scale, r.z * scale, r.w * scale);

    if (final_out)
        reinterpret_cast<float4*>(dout)[b * 256 + t] = o;
    if (ow_mode == 1) {
        reinterpret_cast<float4*>(g_ow)[b * 256 + t] = o;
    } else if (ow_mode == 2) {
        float4 c = reinterpret_cast<const float4*>(g_ow)[b * 256 + t];
        c.x += o.x; c.y += o.y; c.z += o.z; c.w += o.w;
        reinterpret_cast<float4*>(g_ow)[b * 256 + t] = c;
    }

    if (t == 0) g_cnt[b] = 0;   // reset for next round / next graph replay
}

// ---------------------------------------------------------------------------
// Pass kernel: one warp processes IPW contiguous rows of x[b, i, :, :].
// For each row: p_j = dot(x[j,:], ow[j,:]); a = softmax_j(p); acc += a_j * x[j,:].
// uniform=1 (round 0): a = 1/64 exactly (softmax of zero priors).
// Lane mapping: float4 f = lane + 32*k -> j = (lane>>2) + 8k, d = (lane&3)*4.
// ---------------------------------------------------------------------------
__global__ void __launch_bounds__(256, 2)
route_pass(const float* __restrict__ x, const float* __restrict__ bias,
           float* __restrict__ dout, int uniform, int ow_mode, int final_out)
{
    const int b     = blockIdx.x >> 4;           // 16 slices per batch
    const int slice = blockIdx.x & 15;
    const int wloc  = threadIdx.x >> 5;
    const int wb    = (slice << 3) | wloc;       // warp id within b: 0..127
    const int lane  = threadIdx.x & 31;

    float4 w[8];
    if (!uniform) {
        const float4* owp = reinterpret_cast<const float4*>(g_ow) + (size_t)b * (ROW / 4);
#pragma unroll
        for (int k = 0; k < 8; k++) w[k] = owp[lane + 32 * k];
    }

    float4 acc[8];
#pragma unroll
    for (int k = 0; k < 8; k++) acc[k] = make_float4(0.f, 0.f, 0.f, 0.f);

    const float4* base = reinterpret_cast<const float4*>(x)
        + ((size_t)b * NIN + (size_t)wb * IPW) * (ROW / 4);

    for (int ii = 0; ii < IPW; ii++) {
        const float4* rowp = base + (size_t)ii * (ROW / 4);
        float4 xv[8];
#pragma unroll
        for (int k = 0; k < 8; k++) xv[k] = __ldcs(rowp + lane + 32 * k);  // streaming

        float a[8];
        if (uniform) {
#pragma unroll
            for (int k = 0; k < 8; k++) a[k] = 0.015625f;  // 1/64 exact
        } else {
            float p[8];
#pragma unroll
            for (int k = 0; k < 8; k++) {
                float t = xv[k].x * w[k].x + xv[k].y * w[k].y
                        + xv[k].z * w[k].z + xv[k].w * w[k].w;
                t += __shfl_xor_sync(0xffffffffu, t, 1);
                t += __shfl_xor_sync(0xffffffffu, t, 2);
                p[k] = t;   // dot over d=16, replicated within 4-lane group
            }
            // softmax over all 64 j
            float m = p[0];
#pragma unroll
            for (int k = 1; k < 8; k++) m = fmaxf(m, p[k]);
            m = fmaxf(m, __shfl_xor_sync(0xffffffffu, m, 4));
            m = fmaxf(m, __shfl_xor_sync(0xffffffffu, m, 8));
            m = fmaxf(m, __shfl_xor_sync(0xffffffffu, m, 16));
            float s = 0.f;
#pragma unroll
            for (int k = 0; k < 8; k++) { a[k] = __expf(p[k] - m); s += a[k]; }
            s += __shfl_xor_sync(0xffffffffu, s, 4);
            s += __shfl_xor_sync(0xffffffffu, s, 8);
            s += __shfl_xor_sync(0xffffffffu, s, 16);
            float inv = 1.0f / s;
#pragma unroll
            for (int k = 0; k < 8; k++) a[k] *= inv;
        }
#pragma unroll
        for (int k = 0; k < 8; k++) {
            acc[k].x = fmaf(a[k], xv[k].x, acc[k].x);
            acc[k].y = fmaf(a[k], xv[k].y, acc[k].y);
            acc[k].z = fmaf(a[k], xv[k].z, acc[k].z);
            acc[k].w = fmaf(a[k], xv[k].w, acc[k].w);
        }
    }

    finish_tail(b, slice, acc, wloc, lane, bias, dout, ow_mode, final_out);
}

extern "C" void kernel_launch(void* const* d_in, const int* in_sizes, int n_in,
                              void* d_out, int out_size)
{
    const float* x    = (const float*)d_in[0];   // [32, 2048, 64, 16]
    const float* bias = (const float*)d_in[1];   // [64, 16]
    float* out = (float*)d_out;                  // [32, 64, 16]

    (void)in_sizes; (void)n_in; (void)out_size;

    dim3 g(NB * SLICES), blk(256);

    // Round 0: uniform weights (softmax of zero priors = 1/64); g_ow = out0
    route_pass<<<g, blk>>>(x, bias, out, /*uniform=*/1, /*ow_mode=*/1, /*final=*/0);
    // Round 1: softmax(dot(x, out0)); g_ow = out0 + out1
    route_pass<<<g, blk>>>(x, bias, out, /*uniform=*/0, /*ow_mode=*/2, /*final=*/0);
    // Round 2: softmax(dot(x, out0+out1)); write output (priors linear in outs)
    route_pass<<<g, blk>>>(x, bias, out, /*uniform=*/0, /*ow_mode=*/0, /*final=*/1);
}

// round 5
// speedup vs baseline: 1.5132x; 1.1000x over previous
#include <cuda_runtime.h>

// Problem constants
#define NB   32      // batch
#define NIN  2048    // input capsules
#define ROW  1024    // NOUT*DD floats per (b,i) row
#define SLICES 8     // blocks per batch item (grid 256 = one wave @ 2 blocks/SM)
#define WPBLK  8     // warps per block
#define IPW  32      // input rows per warp (NIN / (SLICES*WPBLK))

// Scratch (static device memory; no runtime allocation)
__device__ float g_partials[NB * SLICES * ROW];  // 1 MB, L2-resident
__device__ float g_ow[NB * ROW];                 // out0 (round1) / out0+out1 (round2)
__device__ int   g_cnt[NB];                      // zero-init; self-resetting

// ---------------------------------------------------------------------------
// Fused tail: in-block reduce (8 warps -> 1 partial per block), then the LAST
// block of each batch reduces the SLICES partials in fixed order, adds bias,
// squashes, updates g_ow / writes output, resets the counter (replay-safe).
// ---------------------------------------------------------------------------
template<int OW_MODE, int FINAL_OUT>
__device__ __forceinline__ void finish_tail(
    int b, int slice, float4 acc[8], int wloc, int lane,
    const float* __restrict__ bias, float* __restrict__ dout)
{
    __shared__ float4 sbuf[WPBLK * 256];   // 32 KB
#pragma unroll
    for (int k = 0; k < 8; k++) sbuf[wloc * 256 + lane + 32 * k] = acc[k];
    __syncthreads();

    const int t = threadIdx.x;
    float4 s = make_float4(0.f, 0.f, 0.f, 0.f);
#pragma unroll
    for (int w2 = 0; w2 < WPBLK; w2++) {
        float4 v = sbuf[w2 * 256 + t];
        s.x += v.x; s.y += v.y; s.z += v.z; s.w += v.w;
    }
    reinterpret_cast<float4*>(g_partials)[((size_t)b * SLICES + slice) * 256 + t] = s;
    __threadfence();

    __shared__ int isLast;
    if (t == 0) {
        int old = atomicAdd(&g_cnt[b], 1);
        isLast = (old == SLICES - 1);
    }
    __syncthreads();
    if (!isLast) return;

    // Last block for this batch: all partials visible (fence + atomic order).
    const float4* pp = reinterpret_cast<const float4*>(g_partials) + (size_t)b * SLICES * 256;
    float4 r = make_float4(0.f, 0.f, 0.f, 0.f);
#pragma unroll
    for (int s2 = 0; s2 < SLICES; s2++) {
        float4 v = __ldcg(pp + s2 * 256 + t);   // L2 (other SMs wrote these)
        r.x += v.x; r.y += v.y; r.z += v.z; r.w += v.w;
    }
    float4 bb = reinterpret_cast<const float4*>(bias)[t];
    r.x += bb.x; r.y += bb.y; r.z += bb.z; r.w += bb.w;

    // squash over d=16 (4 threads per capsule j)
    float n2 = r.x * r.x + r.y * r.y + r.z * r.z + r.w * r.w;
    n2 += __shfl_xor_sync(0xffffffffu, n2, 1);
    n2 += __shfl_xor_sync(0xffffffffu, n2, 2);
    float scale = n2 / ((1.0f + n2) * sqrtf(n2 + 1e-7f));
    float4 o = make_float4(r.x * scale, r.y * scale, r.z * scale, r.w * scale);

    if (FINAL_OUT)
        reinterpret_cast<float4*>(dout)[b * 256 + t] = o;
    if (OW_MODE == 1) {
        reinterpret_cast<float4*>(g_ow)[b * 256 + t] = o;
    } else if (OW_MODE == 2) {
        float4 c = reinterpret_cast<const float4*>(g_ow)[b * 256 + t];
        c.x += o.x; c.y += o.y; c.z += o.z; c.w += o.w;
        reinterpret_cast<float4*>(g_ow)[b * 256 + t] = c;
    }

    if (t == 0) g_cnt[b] = 0;   // reset for next round / next graph replay
}

// ---------------------------------------------------------------------------
// Pass kernel: one warp processes IPW contiguous rows of x[b, i, :, :].
// For each row: p_j = dot(x[j,:], ow[j,:]); a = softmax_j(p); acc += a_j * x[j,:].
// UNIFORM=1 (round 0): a = 1/64 exactly (softmax of zero priors) -- the whole
// weight/softmax path is compiled out.
// Lane mapping: float4 f = lane + 32*k -> j = (lane>>2) + 8k, d = (lane&3)*4.
// ---------------------------------------------------------------------------
template<int UNIFORM, int OW_MODE, int FINAL_OUT>
__global__ void __launch_bounds__(256, 2)
route_pass(const float* __restrict__ x, const float* __restrict__ bias,
           float* __restrict__ dout)
{
    const int b     = blockIdx.x >> 3;
    const int slice = blockIdx.x & 7;
    const int wloc  = threadIdx.x >> 5;
    const int wb    = (slice << 3) | wloc;       // warp id within b: 0..63
    const int lane  = threadIdx.x & 31;

    float4 w[8];
    if (!UNIFORM) {
        const float4* owp = reinterpret_cast<const float4*>(g_ow) + (size_t)b * (ROW / 4);
#pragma unroll
        for (int k = 0; k < 8; k++) w[k] = owp[lane + 32 * k];
    }

    float4 acc[8];
#pragma unroll
    for (int k = 0; k < 8; k++) acc[k] = make_float4(0.f, 0.f, 0.f, 0.f);

    const float4* base = reinterpret_cast<const float4*>(x)
        + ((size_t)b * NIN + (size_t)wb * IPW) * (ROW / 4);

    for (int ii = 0; ii < IPW; ii++) {
        const float4* rowp = base + (size_t)ii * (ROW / 4);
        float4 xv[8];
#pragma unroll
        for (int k = 0; k < 8; k++) xv[k] = __ldcs(rowp + lane + 32 * k);  // streaming

        if (UNIFORM) {
#pragma unroll
            for (int k = 0; k < 8; k++) {
                acc[k].x += xv[k].x; acc[k].y += xv[k].y;
                acc[k].z += xv[k].z; acc[k].w += xv[k].w;
            }
        } else {
            float p[8];
#pragma unroll
            for (int k = 0; k < 8; k++) {
                float t = xv[k].x * w[k].x + xv[k].y * w[k].y
                        + xv[k].z * w[k].z + xv[k].w * w[k].w;
                t += __shfl_xor_sync(0xffffffffu, t, 1);
                t += __shfl_xor_sync(0xffffffffu, t, 2);
                p[k] = t;   // dot over d=16, replicated within 4-lane group
            }
            // softmax over all 64 j
            float m = p[0];
#pragma unroll
            for (int k = 1; k < 8; k++) m = fmaxf(m, p[k]);
            m = fmaxf(m, __shfl_xor_sync(0xffffffffu, m, 4));
            m = fmaxf(m, __shfl_xor_sync(0xffffffffu, m, 8));
            m = fmaxf(m, __shfl_xor_sync(0xffffffffu, m, 16));
            float a[8], s = 0.f;
#pragma unroll
            for (int k = 0; k < 8; k++) { a[k] = __expf(p[k] - m); s += a[k]; }
            s += __shfl_xor_sync(0xffffffffu, s, 4);
            s += __shfl_xor_sync(0xffffffffu, s, 8);
            s += __shfl_xor_sync(0xffffffffu, s, 16);
            float inv = 1.0f / s;
#pragma unroll
            for (int k = 0; k < 8; k++) {
                float ak = a[k] * inv;
                acc[k].x = fmaf(ak, xv[k].x, acc[k].x);
                acc[k].y = fmaf(ak, xv[k].y, acc[k].y);
                acc[k].z = fmaf(ak, xv[k].z, acc[k].z);
                acc[k].w = fmaf(ak, xv[k].w, acc[k].w);
            }
        }
    }

    if (UNIFORM) {
#pragma unroll
        for (int k = 0; k < 8; k++) {
            acc[k].x *= 0.015625f; acc[k].y *= 0.015625f;   // 1/64 exact
            acc[k].z *= 0.015625f; acc[k].w *= 0.015625f;
        }
    }

    finish_tail<OW_MODE, FINAL_OUT>(b, slice, acc, wloc, lane, bias, dout);
}

extern "C" void kernel_launch(void* const* d_in, const int* in_sizes, int n_in,
                              void* d_out, int out_size)
{
    const float* x    = (const float*)d_in[0];   // [32, 2048, 64, 16]
    const float* bias = (const float*)d_in[1];   // [64, 16]
    float* out = (float*)d_out;                  // [32, 64, 16]

    (void)in_sizes; (void)n_in; (void)out_size;

    dim3 g(NB * SLICES), blk(256);

    // Round 0: uniform weights (softmax of zero priors = 1/64); g_ow = out0
    route_pass<1, 1, 0><<<g, blk>>>(x, bias, out);
    // Round 1: softmax(dot(x, out0)); g_ow = out0 + out1
    route_pass<0, 2, 0><<<g, blk>>>(x, bias, out);
    // Round 2: softmax(dot(x, out0+out1)); write output (priors linear in outs)
    route_pass<0, 0, 1><<<g, blk>>>(x, bias, out);
}

// round 6
// speedup vs baseline: 1.6610x; 1.0976x over previous
#include <cuda_runtime.h>

// Problem constants
#define NB   32      // batch
#define NIN  2048    // input capsules
#define ROW  1024    // NOUT*DD floats per (b,i) row
#define SLICES 8     // blocks per batch item (grid 256 = one wave @ 2 blocks/SM)
#define WPBLK  8     // warps per block
#define IPW  32      // input rows per warp (NIN / (SLICES*WPBLK))

// Scratch (static device memory; no runtime allocation)
__device__ float g_partials[NB * SLICES * ROW];  // 1 MB, L2-resident
__device__ float g_ow[NB * ROW];                 // out0 (round1) / out0+out1 (round2)
__device__ int   g_cnt[NB];                      // zero-init; self-resetting

// ---------------------------------------------------------------------------
// Fused tail: in-block reduce (8 warps -> 1 partial per block), then the LAST
// block of each batch reduces the SLICES partials in fixed order, adds bias,
// squashes, updates g_ow / writes output, resets the counter (replay-safe).
// ---------------------------------------------------------------------------
template<int OW_MODE, int FINAL_OUT>
__device__ __forceinline__ void finish_tail(
    int b, int slice, float4 acc[8], int wloc, int lane,
    const float* __restrict__ bias, float* __restrict__ dout)
{
    __shared__ float4 sbuf[WPBLK * 256];   // 32 KB
#pragma unroll
    for (int k = 0; k < 8; k++) sbuf[wloc * 256 + lane + 32 * k] = acc[k];
    __syncthreads();

    const int t = threadIdx.x;
    float4 s = make_float4(0.f, 0.f, 0.f, 0.f);
#pragma unroll
    for (int w2 = 0; w2 < WPBLK; w2++) {
        float4 v = sbuf[w2 * 256 + t];
        s.x += v.x; s.y += v.y; s.z += v.z; s.w += v.w;
    }
    reinterpret_cast<float4*>(g_partials)[((size_t)b * SLICES + slice) * 256 + t] = s;
    __threadfence();

    __shared__ int isLast;
    if (t == 0) {
        int old = atomicAdd(&g_cnt[b], 1);
        isLast = (old == SLICES - 1);
    }
    __syncthreads();
    if (!isLast) return;

    // Last block for this batch: all partials visible (fence + atomic order).
    const float4* pp = reinterpret_cast<const float4*>(g_partials) + (size_t)b * SLICES * 256;
    float4 r = make_float4(0.f, 0.f, 0.f, 0.f);
#pragma unroll
    for (int s2 = 0; s2 < SLICES; s2++) {
        float4 v = __ldcg(pp + s2 * 256 + t);   // L2 (other SMs wrote these)
        r.x += v.x; r.y += v.y; r.z += v.z; r.w += v.w;
    }
    float4 bb = reinterpret_cast<const float4*>(bias)[t];
    r.x += bb.x; r.y += bb.y; r.z += bb.z; r.w += bb.w;

    // squash over d=16 (4 threads per capsule j)
    float n2 = r.x * r.x + r.y * r.y + r.z * r.z + r.w * r.w;
    n2 += __shfl_xor_sync(0xffffffffu, n2, 1);
    n2 += __shfl_xor_sync(0xffffffffu, n2, 2);
    float scale = n2 / ((1.0f + n2) * sqrtf(n2 + 1e-7f));
    float4 o = make_float4(r.x * scale, r.y * scale, r.z * scale, r.w * scale);

    if (FINAL_OUT)
        reinterpret_cast<float4*>(dout)[b * 256 + t] = o;
    if (OW_MODE == 1) {
        reinterpret_cast<float4*>(g_ow)[b * 256 + t] = o;
    } else if (OW_MODE == 2) {
        float4 c = reinterpret_cast<const float4*>(g_ow)[b * 256 + t];
        c.x += o.x; c.y += o.y; c.z += o.z; c.w += o.w;
        reinterpret_cast<float4*>(g_ow)[b * 256 + t] = c;
    }

    if (t == 0) g_cnt[b] = 0;   // reset for next round / next graph replay
}

// ---------------------------------------------------------------------------
// Pass kernel: one warp processes IPW contiguous rows of x[b, i, :, :].
// For each row: p_j = dot(x[j,:], ow[j,:]); a = softmax_j(p); acc += a_j * x[j,:].
// UNIFORM=1 (round 0): a = 1/64 exactly (softmax of zero priors).
// REVERSE: traverse the warp's row range back-to-front. Passes zigzag
// (fwd, rev, fwd) so each pass starts on the data its predecessor left in L2.
// Plain loads (no __ldcs) so L2 retains the stream tail across passes.
// Lane mapping: float4 f = lane + 32*k -> j = (lane>>2) + 8k, d = (lane&3)*4.
// ---------------------------------------------------------------------------
template<int UNIFORM, int OW_MODE, int FINAL_OUT, int REVERSE>
__global__ void __launch_bounds__(256, 2)
route_pass(const float* __restrict__ x, const float* __restrict__ bias,
           float* __restrict__ dout)
{
    const int b     = blockIdx.x >> 3;
    const int slice = blockIdx.x & 7;
    const int wloc  = threadIdx.x >> 5;
    const int wb    = (slice << 3) | wloc;       // warp id within b: 0..63
    const int lane  = threadIdx.x & 31;

    float4 w[8];
    if (!UNIFORM) {
        const float4* owp = reinterpret_cast<const float4*>(g_ow) + (size_t)b * (ROW / 4);
#pragma unroll
        for (int k = 0; k < 8; k++) w[k] = owp[lane + 32 * k];
    }

    float4 acc[8];
#pragma unroll
    for (int k = 0; k < 8; k++) acc[k] = make_float4(0.f, 0.f, 0.f, 0.f);

    const float4* base = reinterpret_cast<const float4*>(x)
        + ((size_t)b * NIN + (size_t)wb * IPW) * (ROW / 4);

    for (int it = 0; it < IPW; it++) {
        const int ii = REVERSE ? (IPW - 1 - it) : it;
        const float4* rowp = base + (size_t)ii * (ROW / 4);
        float4 xv[8];
#pragma unroll
        for (int k = 0; k < 8; k++) xv[k] = rowp[lane + 32 * k];   // default policy: allow L2 retention

        if (UNIFORM) {
#pragma unroll
            for (int k = 0; k < 8; k++) {
                acc[k].x += xv[k].x; acc[k].y += xv[k].y;
                acc[k].z += xv[k].z; acc[k].w += xv[k].w;
            }
        } else {
            float p[8];
#pragma unroll
            for (int k = 0; k < 8; k++) {
                float t = xv[k].x * w[k].x + xv[k].y * w[k].y
                        + xv[k].z * w[k].z + xv[k].w * w[k].w;
                t += __shfl_xor_sync(0xffffffffu, t, 1);
                t += __shfl_xor_sync(0xffffffffu, t, 2);
                p[k] = t;   // dot over d=16, replicated within 4-lane group
            }
            // softmax over all 64 j
            float m = p[0];
#pragma unroll
            for (int k = 1; k < 8; k++) m = fmaxf(m, p[k]);
            m = fmaxf(m, __shfl_xor_sync(0xffffffffu, m, 4));
            m = fmaxf(m, __shfl_xor_sync(0xffffffffu, m, 8));
            m = fmaxf(m, __shfl_xor_sync(0xffffffffu, m, 16));
            float a[8], s = 0.f;
#pragma unroll
            for (int k = 0; k < 8; k++) { a[k] = __expf(p[k] - m); s += a[k]; }
            s += __shfl_xor_sync(0xffffffffu, s, 4);
            s += __shfl_xor_sync(0xffffffffu, s, 8);
            s += __shfl_xor_sync(0xffffffffu, s, 16);
            float inv = 1.0f / s;
#pragma unroll
            for (int k = 0; k < 8; k++) {
                float ak = a[k] * inv;
                acc[k].x = fmaf(ak, xv[k].x, acc[k].x);
                acc[k].y = fmaf(ak, xv[k].y, acc[k].y);
                acc[k].z = fmaf(ak, xv[k].z, acc[k].z);
                acc[k].w = fmaf(ak, xv[k].w, acc[k].w);
            }
        }
    }

    if (UNIFORM) {
#pragma unroll
        for (int k = 0; k < 8; k++) {
            acc[k].x *= 0.015625f; acc[k].y *= 0.015625f;   // 1/64 exact
            acc[k].z *= 0.015625f; acc[k].w *= 0.015625f;
        }
    }

    finish_tail<OW_MODE, FINAL_OUT>(b, slice, acc, wloc, lane, bias, dout);
}

extern "C" void kernel_launch(void* const* d_in, const int* in_sizes, int n_in,
                              void* d_out, int out_size)
{
    const float* x    = (const float*)d_in[0];   // [32, 2048, 64, 16]
    const float* bias = (const float*)d_in[1];   // [64, 16]
    float* out = (float*)d_out;                  // [32, 64, 16]

    (void)in_sizes; (void)n_in; (void)out_size;

    dim3 g(NB * SLICES), blk(256);

    // Round 0 (forward): uniform weights (softmax of zero priors = 1/64); g_ow = out0
    route_pass<1, 1, 0, 0><<<g, blk>>>(x, bias, out);
    // Round 1 (REVERSE): softmax(dot(x, out0)); g_ow = out0 + out1
    //   starts on the stream tail pass 0 left in L2
    route_pass<0, 2, 0, 1><<<g, blk>>>(x, bias, out);
    // Round 2 (forward): softmax(dot(x, out0+out1)); write output
    //   starts on the stream head pass 1 left in L2
    route_pass<0, 0, 1, 0><<<g, blk>>>(x, bias, out);
}